// round 7
// baseline (speedup 1.0000x reference)
#include <cuda_runtime.h>
#include <cuda_bf16.h>
#include <cstdint>

// Problem constants
#define IDIM   80
#define HDIM   512
#define WIN    160      // IN_EXTRA + IDIM
#define NSHIFT 81       // IN_EXTRA + 1
#define NTOK   2048     // B*T
#define KSEL   128      // 2*CDIM
#define TPB    8        // tokens per hcompute block

// ---------------- scratch (__device__ globals; no allocation) ----------------
__device__ float g_C[WIN * WIN];            // Gram matrix W_enc^T W_enc (160x160)
__device__ float g_v[WIN];                  // W_enc^T b_enc
__device__ unsigned long long g_packed[NTOK]; // (ordered(E)<<32)|q  via atomicMax
__device__ float g_WeT[WIN * HDIM];         // W_enc transposed
__device__ float g_WdT[HDIM * WIN];         // W_dec transposed
__device__ float g_h[NTOK * HDIM];          // masked h per token

// ---------------- K1: fused prep (gram + transposes + vb + zero) ----------------
__global__ __launch_bounds__(256) void prep_kernel(
    const float* __restrict__ W_enc, const float* __restrict__ b_enc,
    const float* __restrict__ W_dec)
{
    int blk = blockIdx.x;
    int tid = threadIdx.x;

    if (blk < 25) {
        __shared__ float SA[8][32];
        __shared__ float SB[8][32];
        int d0 = (blk % 5) * 32, e0 = (blk / 5) * 32;
        int dd = tid >> 5, ee = tid & 31;
        float a0 = 0.f, a1 = 0.f, a2 = 0.f, a3 = 0.f;
        for (int j0 = 0; j0 < HDIM; j0 += 8) {
            SA[dd][ee] = W_enc[(j0 + dd) * WIN + d0 + ee];
            SB[dd][ee] = W_enc[(j0 + dd) * WIN + e0 + ee];
            __syncthreads();
#pragma unroll
            for (int jj = 0; jj < 8; jj++) {
                float b = SB[jj][ee];
                a0 += SA[jj][dd] * b;
                a1 += SA[jj][dd + 8] * b;
                a2 += SA[jj][dd + 16] * b;
                a3 += SA[jj][dd + 24] * b;
            }
            __syncthreads();
        }
        g_C[(d0 + dd) * WIN + e0 + ee]      = a0;
        g_C[(d0 + dd + 8) * WIN + e0 + ee]  = a1;
        g_C[(d0 + dd + 16) * WIN + e0 + ee] = a2;
        g_C[(d0 + dd + 24) * WIN + e0 + ee] = a3;
    } else if (blk < 105) {
        __shared__ float tile[32][33];
        int bi = blk - 25;
        int bx = (bi % 5) * 32;
        int by = (bi / 5) * 32;
        int tx = tid & 31, ty = tid >> 5;
#pragma unroll
        for (int r = 0; r < 4; r++)
            tile[ty + 8 * r][tx] = W_enc[(by + ty + 8 * r) * WIN + bx + tx];
        __syncthreads();
#pragma unroll
        for (int r = 0; r < 4; r++)
            g_WeT[(bx + ty + 8 * r) * HDIM + by + tx] = tile[tx][ty + 8 * r];
    } else if (blk < 185) {
        __shared__ float tile[32][33];
        int bi = blk - 105;
        int bx = (bi / 5) * 32;
        int by = (bi % 5) * 32;
        int tx = tid & 31, ty = tid >> 5;
#pragma unroll
        for (int r = 0; r < 4; r++)
            tile[ty + 8 * r][tx] = W_dec[(by + ty + 8 * r) * HDIM + bx + tx];
        __syncthreads();
#pragma unroll
        for (int r = 0; r < 4; r++)
            g_WdT[(bx + ty + 8 * r) * WIN + by + tx] = tile[tx][ty + 8 * r];
    } else if (blk < 345) {
        __shared__ float red[256];
        int d = blk - 185;
        float a = b_enc[tid] * W_enc[tid * WIN + d]
                + b_enc[tid + 256] * W_enc[(tid + 256) * WIN + d];
        red[tid] = a;
        __syncthreads();
        for (int o = 128; o > 0; o >>= 1) {
            if (tid < o) red[tid] += red[tid + o];
            __syncthreads();
        }
        if (tid == 0) g_v[d] = red[0];
    } else {
        for (int i = tid; i < NTOK; i += 256) g_packed[i] = 0ull;
    }
}

// ---------------- K2: energies via symmetric Gram triangle + fused argmax ----------------
// E(t,s) = 2*( sum_i x_i*(0.5*C[q+i][q+i]*x_i + sum_{k>i} C[q+i][q+k]*x_k) + v[q:].x )
// x in an 80-register array (static indices via full unroll); C reads are scalar
// broadcast LDS with immediate offsets. atomicMax on (ordered(E)<<32)|q.
#define NS 8
#define CROWS 87
#define CPITCH 96
__global__ __launch_bounds__(128) void energy_kernel(const float* __restrict__ x) {
    __shared__ float Cs[CROWS * CPITCH];
    __shared__ float xs[32 * 81];
    __shared__ float vs[WIN];

    int tid = threadIdx.x;
    int lane = tid & 31;
    int w = tid >> 5;
    int tb = blockIdx.x * 32;
    int s0 = blockIdx.y * NS;
    int qlo = 73 - s0; if (qlo < 0) qlo = 0;

    for (int i = tid; i < CROWS * CROWS; i += 128) {
        int r = i / CROWS, c = i - r * CROWS;
        Cs[r * CPITCH + 4 + c] = g_C[(qlo + r) * WIN + qlo + c];
    }
    for (int i = tid; i < 32 * IDIM; i += 128) {
        int tok = i / IDIM, ii = i - tok * IDIM;
        xs[tok * 81 + ii] = x[(tb + tok) * IDIM + ii];
    }
    for (int i = tid; i < WIN; i += 128) vs[i] = g_v[i];
    __syncthreads();

    const float* myx = &xs[lane * 81];   // stride 81 floats -> conflict-free
    float xv[IDIM];
#pragma unroll
    for (int i = 0; i < IDIM; i++) xv[i] = myx[i];

    unsigned long long best = 0ull;

#pragma unroll 1
    for (int si = 0; si < 2; si++) {
        int s = s0 + w + si * 4;
        if (s > 80) continue;
        int q = 80 - s;
        int coff = q - qlo;           // 0..7
        // crow[i*CPITCH + k] == Cs[(coff+i)*CPITCH + 4 + coff + k] == C[q+i][q+k]
        const float* crow = &Cs[coff * (CPITCH + 1) + 4];

        float acc0 = 0.f, acc1 = 0.f, acc2 = 0.f, acc3 = 0.f;
#pragma unroll
        for (int i = 0; i < IDIM; i++) {
            float r = 0.5f * crow[i * CPITCH + i] * xv[i];
#pragma unroll
            for (int k = i + 1; k < IDIM; k++)
                r += crow[i * CPITCH + k] * xv[k];
            float term = xv[i] * r;
            if ((i & 3) == 0) acc0 += term;
            else if ((i & 3) == 1) acc1 += term;
            else if ((i & 3) == 2) acc2 += term;
            else acc3 += term;
        }

        float cross = 0.f;
#pragma unroll
        for (int i = 0; i < IDIM; i++) cross += xv[i] * vs[q + i];

        float E = 2.f * (((acc0 + acc1) + (acc2 + acc3)) + cross);

        unsigned eb = __float_as_uint(E);
        unsigned key = eb ^ (unsigned)(((int)eb >> 31) | 0x80000000);
        unsigned long long pk = ((unsigned long long)key << 32) | (unsigned)q;
        if (pk > best) best = pk;
    }
    if (best) atomicMax(&g_packed[tb + lane], best);
}

// ---------------- K3: h for winning shift, 8 tokens/block, coalesced WeT ----------------
__global__ __launch_bounds__(256) void hcompute_kernel(
    const float* __restrict__ x, const float* __restrict__ b_enc,
    const int* __restrict__ mask_prev)
{
    __shared__ float xsp[TPB][WIN];
    __shared__ int qs[TPB];
    int tid = threadIdx.x;
    int tb = blockIdx.x * TPB;

    if (tid < TPB) qs[tid] = (int)(g_packed[tb + tid] & 0xFFFFFFFFull);
    for (int i = tid; i < TPB * WIN; i += 256) ((float*)xsp)[i] = 0.f;
    __syncthreads();
    for (int idx = tid; idx < TPB * IDIM; idx += 256) {
        int t = idx / IDIM, a = idx - t * IDIM;
        xsp[t][qs[t] + a] = x[(tb + t) * IDIM + a];
    }
    __syncthreads();

    int j0 = 2 * tid;
    float a0[TPB], a1[TPB];
#pragma unroll
    for (int t = 0; t < TPB; t++) { a0[t] = 0.f; a1[t] = 0.f; }

    for (int i = 0; i < WIN; i++) {
        float2 c = *reinterpret_cast<const float2*>(&g_WeT[i * HDIM + j0]);
#pragma unroll
        for (int t = 0; t < TPB; t++) {
            float xv = xsp[t][i];
            a0[t] += xv * c.x;
            a1[t] += xv * c.y;
        }
    }

    float bb0 = b_enc[j0], bb1 = b_enc[j0 + 1];
#pragma unroll
    for (int t = 0; t < TPB; t++) {
        int tg = tb + t;
        int2 m = *reinterpret_cast<const int2*>(&mask_prev[tg * HDIM + j0]);
        float h0 = a0[t] + bb0; if (m.x != 0) h0 = 0.f;
        float h1 = a1[t] + bb1; if (m.y != 0) h1 = 0.f;
        *reinterpret_cast<float2*>(&g_h[tg * HDIM + j0]) = make_float2(h0, h1);
    }
}

// ---------------- K4: exact top-128 via MSD radix select + sparse decoder ----------------
__global__ __launch_bounds__(256) void sortdecode_kernel(
    const float* __restrict__ b_dec, float* __restrict__ out)
{
    __shared__ unsigned vals[HDIM];
    __shared__ float hs[HDIM];
    __shared__ int hist[256];
    __shared__ unsigned selbits[16];
    __shared__ unsigned eqbits[16];
    __shared__ int sPrefix, sR, sGt;
    __shared__ float selv[KSEL];
    __shared__ int   selj[KSEL];
    __shared__ float psum[240];

    int t = blockIdx.x;
    int tid = threadIdx.x;
    int q = (int)(g_packed[t] & 0xFFFFFFFFull);

    float h0 = g_h[t * HDIM + tid];
    float h1 = g_h[t * HDIM + tid + 256];
    hs[tid] = h0;
    hs[tid + 256] = h1;
    unsigned v0 = __float_as_uint(h0 * h0);   // >=0 -> bit-monotonic
    unsigned v1 = __float_as_uint(h1 * h1);
    vals[tid] = v0;
    vals[tid + 256] = v1;
    if (tid == 0) { sPrefix = 0; sR = KSEL; sGt = 0; }
    if (tid < 16) { selbits[tid] = 0u; eqbits[tid] = 0u; }
    __syncthreads();

#pragma unroll
    for (int pass = 0; pass < 4; pass++) {
        int shift = 24 - 8 * pass;
        if (tid < 256) hist[tid] = 0;
        __syncthreads();
        int prefix = sPrefix;
        bool act0 = (pass == 0) || ((v0 >> (shift + 8)) == (unsigned)(prefix >> (shift + 8)));
        bool act1 = (pass == 0) || ((v1 >> (shift + 8)) == (unsigned)(prefix >> (shift + 8)));
        if (act0) atomicAdd(&hist[(v0 >> shift) & 255], 1);
        if (act1) atomicAdd(&hist[(v1 >> shift) & 255], 1);
        __syncthreads();
        if (tid < 32) {
            int lane = tid;
            int base = 255 - lane * 8;
            int c[8], lsum = 0;
#pragma unroll
            for (int i = 0; i < 8; i++) { c[i] = hist[base - i]; lsum += c[i]; }
            int xsc = lsum;
#pragma unroll
            for (int o = 1; o < 32; o <<= 1) {
                int y = __shfl_up_sync(0xffffffffu, xsc, o);
                if (lane >= o) xsc += y;
            }
            int pref = xsc - lsum;
            int r = sR;
            if (pref < r && r <= pref + lsum) {
                int run = pref, d = -1, gt_add = 0;
#pragma unroll
                for (int i = 0; i < 8; i++) {
                    if (d < 0 && run + c[i] >= r) { d = base - i; gt_add = run; }
                    run += c[i];
                }
                sPrefix = prefix | (d << shift);
                sR = r - gt_add;
                sGt = sGt + gt_add;
            }
        }
        __syncthreads();
    }

    unsigned Tv = (unsigned)sPrefix;
    int need_eq = KSEL - sGt;

    if (v0 > Tv) atomicOr(&selbits[tid >> 5], 1u << (tid & 31));
    else if (v0 == Tv) atomicOr(&eqbits[tid >> 5], 1u << (tid & 31));
    {
        int j = tid + 256;
        if (v1 > Tv) atomicOr(&selbits[j >> 5], 1u << (j & 31));
        else if (v1 == Tv) atomicOr(&eqbits[j >> 5], 1u << (j & 31));
    }
    __syncthreads();

#pragma unroll
    for (int e = 0; e < 2; e++) {
        int j = tid + 256 * e;
        unsigned vv = (e == 0) ? v0 : v1;
        if (vv == Tv) {
            int w = j >> 5;
            int rk = __popc(eqbits[w] & ((1u << (j & 31)) - 1u));
            for (int u = 0; u < w; u++) rk += __popc(eqbits[u]);
            if (rk < need_eq) atomicOr(&selbits[w], 1u << (j & 31));
        }
    }
    __syncthreads();

#pragma unroll
    for (int e = 0; e < 2; e++) {
        int j = tid + 256 * e;
        int w = j >> 5;
        if (selbits[w] & (1u << (j & 31))) {
            int slot = __popc(selbits[w] & ((1u << (j & 31)) - 1u));
            for (int u = 0; u < w; u++) slot += __popc(selbits[u]);
            selj[slot] = j;
            selv[slot] = hs[j];
        }
    }
    __syncthreads();

    if (tid < 240) {
        int g = tid / IDIM;
        int i = tid - g * IDIM;
        int k0 = (g == 0) ? 0 : (g == 1 ? 43 : 86);
        int k1 = (g == 0) ? 43 : (g == 1 ? 86 : KSEL);
        float a = 0.f;
        for (int k = k0; k < k1; k++)
            a += selv[k] * g_WdT[selj[k] * WIN + q + i];
        psum[tid] = a;
    }
    __syncthreads();
    if (tid < IDIM)
        out[t * IDIM + tid] = psum[tid] + psum[IDIM + tid] + psum[2 * IDIM + tid]
                            + b_dec[q + tid];
}

// ---------------- launch ----------------
extern "C" void kernel_launch(void* const* d_in, const int* in_sizes, int n_in,
                              void* d_out, int out_size) {
    const float* x        = (const float*)d_in[0];
    const float* W_enc    = (const float*)d_in[1];
    const float* b_enc    = (const float*)d_in[2];
    const float* W_dec    = (const float*)d_in[3];
    const float* b_dec    = (const float*)d_in[4];
    const int*   mask_prev= (const int*)d_in[5];
    float* out = (float*)d_out;

    prep_kernel<<<346, 256>>>(W_enc, b_enc, W_dec);
    energy_kernel<<<dim3(64, 11), 128>>>(x);
    hcompute_kernel<<<NTOK / TPB, 256>>>(x, b_enc, mask_prev);
    sortdecode_kernel<<<NTOK, 256>>>(b_dec, out);   // profiled launch (#4)
}

// round 8
// speedup vs baseline: 2.0316x; 2.0316x over previous
#include <cuda_runtime.h>
#include <cuda_bf16.h>
#include <cstdint>

// Problem constants
#define IDIM   80
#define HDIM   512
#define WIN    160      // IN_EXTRA + IDIM
#define NSHIFT 81       // IN_EXTRA + 1
#define NTOK   2048     // B*T
#define KSEL   128      // 2*CDIM
#define TPB    8        // tokens per hcompute block

// packed f32x2 helpers (Blackwell sm_100a+)
#define FFMA2_ACC(acc, a, b) \
    asm("fma.rn.f32x2 %0, %1, %2, %0;" : "+l"(acc) : "l"(a), "l"(b))
#define ADD2(d, a, b) \
    asm("add.rn.f32x2 %0, %1, %2;" : "=l"(d) : "l"(a), "l"(b))
#define PACK2(d, lo, hi) \
    asm("mov.b64 %0, {%1, %2};" : "=l"(d) : "f"(lo), "f"(hi))
#define UNPACK2(lo, hi, v) \
    asm("mov.b64 {%0, %1}, %2;" : "=f"(lo), "=f"(hi) : "l"(v))

// ---------------- scratch (__device__ globals; no allocation) ----------------
__device__ float g_C[WIN * WIN];            // Gram matrix W_enc^T W_enc (160x160)
__device__ float g_v[WIN];                  // W_enc^T b_enc
__device__ unsigned long long g_packed[NTOK]; // (ordered(E)<<32)|q  via atomicMax
__device__ float g_WeT[WIN * HDIM];         // W_enc transposed
__device__ float g_WdT[HDIM * WIN];         // W_dec transposed
__device__ float g_h[NTOK * HDIM];          // masked h per token

// ---------------- K1: fused prep (gram + transposes + vb + zero) ----------------
__global__ __launch_bounds__(256) void prep_kernel(
    const float* __restrict__ W_enc, const float* __restrict__ b_enc,
    const float* __restrict__ W_dec)
{
    int blk = blockIdx.x;
    int tid = threadIdx.x;

    if (blk < 25) {
        __shared__ float SA[8][32];
        __shared__ float SB[8][32];
        int d0 = (blk % 5) * 32, e0 = (blk / 5) * 32;
        int dd = tid >> 5, ee = tid & 31;
        float a0 = 0.f, a1 = 0.f, a2 = 0.f, a3 = 0.f;
        for (int j0 = 0; j0 < HDIM; j0 += 8) {
            SA[dd][ee] = W_enc[(j0 + dd) * WIN + d0 + ee];
            SB[dd][ee] = W_enc[(j0 + dd) * WIN + e0 + ee];
            __syncthreads();
#pragma unroll
            for (int jj = 0; jj < 8; jj++) {
                float b = SB[jj][ee];
                a0 += SA[jj][dd] * b;
                a1 += SA[jj][dd + 8] * b;
                a2 += SA[jj][dd + 16] * b;
                a3 += SA[jj][dd + 24] * b;
            }
            __syncthreads();
        }
        g_C[(d0 + dd) * WIN + e0 + ee]      = a0;
        g_C[(d0 + dd + 8) * WIN + e0 + ee]  = a1;
        g_C[(d0 + dd + 16) * WIN + e0 + ee] = a2;
        g_C[(d0 + dd + 24) * WIN + e0 + ee] = a3;
    } else if (blk < 105) {
        __shared__ float tile[32][33];
        int bi = blk - 25;
        int bx = (bi % 5) * 32;
        int by = (bi / 5) * 32;
        int tx = tid & 31, ty = tid >> 5;
#pragma unroll
        for (int r = 0; r < 4; r++)
            tile[ty + 8 * r][tx] = W_enc[(by + ty + 8 * r) * WIN + bx + tx];
        __syncthreads();
#pragma unroll
        for (int r = 0; r < 4; r++)
            g_WeT[(bx + ty + 8 * r) * HDIM + by + tx] = tile[tx][ty + 8 * r];
    } else if (blk < 185) {
        __shared__ float tile[32][33];
        int bi = blk - 105;
        int bx = (bi / 5) * 32;
        int by = (bi % 5) * 32;
        int tx = tid & 31, ty = tid >> 5;
#pragma unroll
        for (int r = 0; r < 4; r++)
            tile[ty + 8 * r][tx] = W_dec[(by + ty + 8 * r) * HDIM + bx + tx];
        __syncthreads();
#pragma unroll
        for (int r = 0; r < 4; r++)
            g_WdT[(bx + ty + 8 * r) * WIN + by + tx] = tile[tx][ty + 8 * r];
    } else if (blk < 345) {
        __shared__ float red[256];
        int d = blk - 185;
        float a = b_enc[tid] * W_enc[tid * WIN + d]
                + b_enc[tid + 256] * W_enc[(tid + 256) * WIN + d];
        red[tid] = a;
        __syncthreads();
        for (int o = 128; o > 0; o >>= 1) {
            if (tid < o) red[tid] += red[tid + o];
            __syncthreads();
        }
        if (tid == 0) g_v[d] = red[0];
    } else {
        for (int i = tid; i < NTOK; i += 256) g_packed[i] = 0ull;
    }
}

// ---------------- K2: energies via Gram quadratic form (packed f32x2) ----------------
// E(t,s) = x^T C[q:q+80, q:q+80] x + 2 v[q:q+80].x   (const b^T b dropped: argmax-safe)
// R6 indexing: padded-row element m multiplies xr[m] = x[m-p] (p = coff&3 alignment
// shift). Packed: xp[j] = (xr[2j], xr[2j+1]); C row loaded as ulonglong2 (LDS.128 ->
// two b64 halves, no pack MOVs); 42 FFMA2 per row into 2 packed accumulators.
#define NS 8
#define CROWS 87
#define CPITCH 96
__global__ __launch_bounds__(128) void energy_kernel(const float* __restrict__ x) {
    __shared__ __align__(16) float Cs[CROWS * CPITCH];
    __shared__ float xs[32 * 81];
    __shared__ float vs[WIN];

    int tid = threadIdx.x;
    int lane = tid & 31;
    int w = tid >> 5;
    int tb = blockIdx.x * 32;
    int s0 = blockIdx.y * NS;
    int qlo = 73 - s0; if (qlo < 0) qlo = 0;

    // zero (pads must be finite: xr tail zeros multiply them)
    for (int i = tid; i < CROWS * CPITCH; i += 128) Cs[i] = 0.f;
    __syncthreads();
    for (int i = tid; i < CROWS * CROWS; i += 128) {
        int r = i / CROWS, c = i - r * CROWS;
        Cs[r * CPITCH + 4 + c] = g_C[(qlo + r) * WIN + qlo + c];
    }
    for (int i = tid; i < 32 * IDIM; i += 128) {
        int tok = i / IDIM, ii = i - tok * IDIM;
        xs[tok * 81 + ii] = x[(tb + tok) * IDIM + ii];
    }
    for (int i = tid; i < WIN; i += 128) vs[i] = g_v[i];
    __syncthreads();

    const float* myx = &xs[lane * 81];
    unsigned long long best = 0ull;

#pragma unroll 1
    for (int si = 0; si < 2; si++) {
        int s = s0 + w + si * 4;
        if (s > 80) continue;
        int q = 80 - s;
        int coff = q - qlo;           // 0..7
        int p = coff & 3;
        int cbase = 4 + coff - p;     // multiple of 4 -> 16B-aligned loads

        // packed x pairs, pre-shifted by p
        unsigned long long xp[42];
#pragma unroll
        for (int j = 0; j < 42; j++) {
            int k0 = 2 * j - p, k1 = 2 * j + 1 - p;
            float lo = (k0 >= 0 && k0 < IDIM) ? myx[k0] : 0.f;
            float hi = (k1 >= 0 && k1 < IDIM) ? myx[k1] : 0.f;
            PACK2(xp[j], lo, hi);
        }

        float acc = 0.f;
        for (int i = 0; i < IDIM; i++) {
            const ulonglong2* cr =
                reinterpret_cast<const ulonglong2*>(&Cs[(coff + i) * CPITCH + cbase]);
            unsigned long long pa = 0ull, pb = 0ull;   // (0.f,0.f) bit pattern
#pragma unroll
            for (int j4 = 0; j4 < 21; j4++) {
                ulonglong2 cv = cr[j4];
                FFMA2_ACC(pa, cv.x, xp[2 * j4]);
                FFMA2_ACC(pb, cv.y, xp[2 * j4 + 1]);
            }
            unsigned long long ps;
            ADD2(ps, pa, pb);
            float rl, rh;
            UNPACK2(rl, rh, ps);
            acc += myx[i] * (rl + rh);
        }

        float cross = 0.f;
        for (int i = 0; i < IDIM; i++) cross += myx[i] * vs[q + i];
        float E = acc + 2.f * cross;

        unsigned eb = __float_as_uint(E);
        unsigned key = eb ^ (unsigned)(((int)eb >> 31) | 0x80000000);
        unsigned long long pk = ((unsigned long long)key << 32) | (unsigned)q;
        if (pk > best) best = pk;
    }
    if (best) atomicMax(&g_packed[tb + lane], best);
}

// ---------------- K3: h for winning shift, 8 tokens/block, coalesced WeT ----------------
__global__ __launch_bounds__(256) void hcompute_kernel(
    const float* __restrict__ x, const float* __restrict__ b_enc,
    const int* __restrict__ mask_prev)
{
    __shared__ float xsp[TPB][WIN];
    __shared__ int qs[TPB];
    int tid = threadIdx.x;
    int tb = blockIdx.x * TPB;

    if (tid < TPB) qs[tid] = (int)(g_packed[tb + tid] & 0xFFFFFFFFull);
    for (int i = tid; i < TPB * WIN; i += 256) ((float*)xsp)[i] = 0.f;
    __syncthreads();
    for (int idx = tid; idx < TPB * IDIM; idx += 256) {
        int t = idx / IDIM, a = idx - t * IDIM;
        xsp[t][qs[t] + a] = x[(tb + t) * IDIM + a];
    }
    __syncthreads();

    int j0 = 2 * tid;
    float a0[TPB], a1[TPB];
#pragma unroll
    for (int t = 0; t < TPB; t++) { a0[t] = 0.f; a1[t] = 0.f; }

    for (int i = 0; i < WIN; i++) {
        float2 c = *reinterpret_cast<const float2*>(&g_WeT[i * HDIM + j0]);
#pragma unroll
        for (int t = 0; t < TPB; t++) {
            float xv = xsp[t][i];
            a0[t] += xv * c.x;
            a1[t] += xv * c.y;
        }
    }

    float bb0 = b_enc[j0], bb1 = b_enc[j0 + 1];
#pragma unroll
    for (int t = 0; t < TPB; t++) {
        int tg = tb + t;
        int2 m = *reinterpret_cast<const int2*>(&mask_prev[tg * HDIM + j0]);
        float h0 = a0[t] + bb0; if (m.x != 0) h0 = 0.f;
        float h1 = a1[t] + bb1; if (m.y != 0) h1 = 0.f;
        *reinterpret_cast<float2*>(&g_h[tg * HDIM + j0]) = make_float2(h0, h1);
    }
}

// ---------------- K4: exact top-128 via MSD radix select + sparse decoder ----------------
__global__ __launch_bounds__(256) void sortdecode_kernel(
    const float* __restrict__ b_dec, float* __restrict__ out)
{
    __shared__ float hs[HDIM];
    __shared__ int hist[256];
    __shared__ unsigned selbits[16];
    __shared__ unsigned eqbits[16];
    __shared__ int sPrefix, sR, sGt;
    __shared__ float selv[KSEL];
    __shared__ int   selj[KSEL];
    __shared__ float psum[240];

    int t = blockIdx.x;
    int tid = threadIdx.x;
    int q = (int)(g_packed[t] & 0xFFFFFFFFull);

    float h0 = g_h[t * HDIM + tid];
    float h1 = g_h[t * HDIM + tid + 256];
    hs[tid] = h0;
    hs[tid + 256] = h1;
    unsigned v0 = __float_as_uint(h0 * h0);   // >=0 -> bit-monotonic
    unsigned v1 = __float_as_uint(h1 * h1);
    if (tid == 0) { sPrefix = 0; sR = KSEL; sGt = 0; }
    if (tid < 16) { selbits[tid] = 0u; eqbits[tid] = 0u; }
    __syncthreads();

#pragma unroll
    for (int pass = 0; pass < 4; pass++) {
        int shift = 24 - 8 * pass;
        if (tid < 256) hist[tid] = 0;
        __syncthreads();
        int prefix = sPrefix;
        bool act0 = (pass == 0) || ((v0 >> (shift + 8)) == (unsigned)(prefix >> (shift + 8)));
        bool act1 = (pass == 0) || ((v1 >> (shift + 8)) == (unsigned)(prefix >> (shift + 8)));
        if (act0) atomicAdd(&hist[(v0 >> shift) & 255], 1);
        if (act1) atomicAdd(&hist[(v1 >> shift) & 255], 1);
        __syncthreads();
        if (tid < 32) {
            int lane = tid;
            int base = 255 - lane * 8;
            int c[8], lsum = 0;
#pragma unroll
            for (int i = 0; i < 8; i++) { c[i] = hist[base - i]; lsum += c[i]; }
            int xsc = lsum;
#pragma unroll
            for (int o = 1; o < 32; o <<= 1) {
                int y = __shfl_up_sync(0xffffffffu, xsc, o);
                if (lane >= o) xsc += y;
            }
            int pref = xsc - lsum;
            int r = sR;
            if (pref < r && r <= pref + lsum) {
                int run = pref, d = -1, gt_add = 0;
#pragma unroll
                for (int i = 0; i < 8; i++) {
                    if (d < 0 && run + c[i] >= r) { d = base - i; gt_add = run; }
                    run += c[i];
                }
                sPrefix = prefix | (d << shift);
                sR = r - gt_add;
                sGt = sGt + gt_add;
            }
        }
        __syncthreads();
    }

    unsigned Tv = (unsigned)sPrefix;
    int need_eq = KSEL - sGt;

    if (v0 > Tv) atomicOr(&selbits[tid >> 5], 1u << (tid & 31));
    else if (v0 == Tv) atomicOr(&eqbits[tid >> 5], 1u << (tid & 31));
    {
        int j = tid + 256;
        if (v1 > Tv) atomicOr(&selbits[j >> 5], 1u << (j & 31));
        else if (v1 == Tv) atomicOr(&eqbits[j >> 5], 1u << (j & 31));
    }
    __syncthreads();

#pragma unroll
    for (int e = 0; e < 2; e++) {
        int j = tid + 256 * e;
        unsigned vv = (e == 0) ? v0 : v1;
        if (vv == Tv) {
            int w = j >> 5;
            int rk = __popc(eqbits[w] & ((1u << (j & 31)) - 1u));
            for (int u = 0; u < w; u++) rk += __popc(eqbits[u]);
            if (rk < need_eq) atomicOr(&selbits[w], 1u << (j & 31));
        }
    }
    __syncthreads();

#pragma unroll
    for (int e = 0; e < 2; e++) {
        int j = tid + 256 * e;
        int w = j >> 5;
        if (selbits[w] & (1u << (j & 31))) {
            int slot = __popc(selbits[w] & ((1u << (j & 31)) - 1u));
            for (int u = 0; u < w; u++) slot += __popc(selbits[u]);
            selj[slot] = j;
            selv[slot] = hs[j];
        }
    }
    __syncthreads();

    if (tid < 240) {
        int g = tid / IDIM;
        int i = tid - g * IDIM;
        int k0 = (g == 0) ? 0 : (g == 1 ? 43 : 86);
        int k1 = (g == 0) ? 43 : (g == 1 ? 86 : KSEL);
        float a = 0.f;
        for (int k = k0; k < k1; k++)
            a += selv[k] * g_WdT[selj[k] * WIN + q + i];
        psum[tid] = a;
    }
    __syncthreads();
    if (tid < IDIM)
        out[t * IDIM + tid] = psum[tid] + psum[IDIM + tid] + psum[2 * IDIM + tid]
                            + b_dec[q + tid];
}

// ---------------- launch ----------------
extern "C" void kernel_launch(void* const* d_in, const int* in_sizes, int n_in,
                              void* d_out, int out_size) {
    const float* x        = (const float*)d_in[0];
    const float* W_enc    = (const float*)d_in[1];
    const float* b_enc    = (const float*)d_in[2];
    const float* W_dec    = (const float*)d_in[3];
    const float* b_dec    = (const float*)d_in[4];
    const int*   mask_prev= (const int*)d_in[5];
    float* out = (float*)d_out;

    prep_kernel<<<346, 256>>>(W_enc, b_enc, W_dec);
    energy_kernel<<<dim3(64, 11), 128>>>(x);
    hcompute_kernel<<<NTOK / TPB, 256>>>(x, b_enc, mask_prev);
    sortdecode_kernel<<<NTOK, 256>>>(b_dec, out);   // profiled launch (#4)
}

// round 9
// speedup vs baseline: 2.0820x; 1.0248x over previous
#include <cuda_runtime.h>
#include <cuda_bf16.h>
#include <cstdint>

// Problem constants
#define IDIM   80
#define HDIM   512
#define WIN    160      // IN_EXTRA + IDIM
#define NSHIFT 81       // IN_EXTRA + 1
#define NTOK   2048     // B*T
#define KSEL   128      // 2*CDIM
#define TPB    8        // tokens per hcompute block

// packed f32x2 helpers (Blackwell sm_100a+)
#define FFMA2_ACC(acc, a, b) \
    asm("fma.rn.f32x2 %0, %1, %2, %0;" : "+l"(acc) : "l"(a), "l"(b))
#define ADD2(d, a, b) \
    asm("add.rn.f32x2 %0, %1, %2;" : "=l"(d) : "l"(a), "l"(b))
#define PACK2(d, lo, hi) \
    asm("mov.b64 %0, {%1, %2};" : "=l"(d) : "f"(lo), "f"(hi))
#define UNPACK2(lo, hi, v) \
    asm("mov.b64 {%0, %1}, %2;" : "=f"(lo), "=f"(hi) : "l"(v))

// ---------------- scratch (__device__ globals; no allocation) ----------------
__device__ float g_C[WIN * WIN];            // Gram matrix W_enc^T W_enc (160x160)
__device__ float g_v[WIN];                  // W_enc^T b_enc
__device__ unsigned long long g_packed[NTOK]; // (ordered(E)<<32)|q  via atomicMax
__device__ float g_WeT[WIN * HDIM];         // W_enc transposed
__device__ float g_WdT[HDIM * WIN];         // W_dec transposed
__device__ float g_h[NTOK * HDIM];          // masked h per token

// ---------------- K1a: gram + zero ----------------
__global__ __launch_bounds__(256) void prep1_kernel(const float* __restrict__ W_enc) {
    int blk = blockIdx.x;
    int tid = threadIdx.x;
    if (blk < 25) {
        __shared__ float SA[8][32];
        __shared__ float SB[8][32];
        int d0 = (blk % 5) * 32, e0 = (blk / 5) * 32;
        int dd = tid >> 5, ee = tid & 31;
        float a0 = 0.f, a1 = 0.f, a2 = 0.f, a3 = 0.f;
        for (int j0 = 0; j0 < HDIM; j0 += 8) {
            SA[dd][ee] = W_enc[(j0 + dd) * WIN + d0 + ee];
            SB[dd][ee] = W_enc[(j0 + dd) * WIN + e0 + ee];
            __syncthreads();
#pragma unroll
            for (int jj = 0; jj < 8; jj++) {
                float b = SB[jj][ee];
                a0 += SA[jj][dd] * b;
                a1 += SA[jj][dd + 8] * b;
                a2 += SA[jj][dd + 16] * b;
                a3 += SA[jj][dd + 24] * b;
            }
            __syncthreads();
        }
        g_C[(d0 + dd) * WIN + e0 + ee]      = a0;
        g_C[(d0 + dd + 8) * WIN + e0 + ee]  = a1;
        g_C[(d0 + dd + 16) * WIN + e0 + ee] = a2;
        g_C[(d0 + dd + 24) * WIN + e0 + ee] = a3;
    } else {
        for (int i = tid; i < NTOK; i += 256) g_packed[i] = 0ull;
    }
}

// ---------------- K1b: transposes ----------------
__global__ __launch_bounds__(256) void prep2_kernel(
    const float* __restrict__ W_enc, const float* __restrict__ W_dec)
{
    __shared__ float tile[32][33];
    int blk = blockIdx.x;
    int tid = threadIdx.x;
    int tx = tid & 31, ty = tid >> 5;
    if (blk < 80) {
        int bx = (blk % 5) * 32;
        int by = (blk / 5) * 32;
#pragma unroll
        for (int r = 0; r < 4; r++)
            tile[ty + 8 * r][tx] = W_enc[(by + ty + 8 * r) * WIN + bx + tx];
        __syncthreads();
#pragma unroll
        for (int r = 0; r < 4; r++)
            g_WeT[(bx + ty + 8 * r) * HDIM + by + tx] = tile[tx][ty + 8 * r];
    } else {
        int bi = blk - 80;
        int bx = (bi / 5) * 32;
        int by = (bi % 5) * 32;
#pragma unroll
        for (int r = 0; r < 4; r++)
            tile[ty + 8 * r][tx] = W_dec[(by + ty + 8 * r) * HDIM + bx + tx];
        __syncthreads();
#pragma unroll
        for (int r = 0; r < 4; r++)
            g_WdT[(bx + ty + 8 * r) * WIN + by + tx] = tile[tx][ty + 8 * r];
    }
}

// ---------------- K1c: v = W^T b ----------------
__global__ __launch_bounds__(256) void prep3_kernel(
    const float* __restrict__ W_enc, const float* __restrict__ b_enc)
{
    __shared__ float red[256];
    int d = blockIdx.x;
    int tid = threadIdx.x;
    float a = b_enc[tid] * W_enc[tid * WIN + d]
            + b_enc[tid + 256] * W_enc[(tid + 256) * WIN + d];
    red[tid] = a;
    __syncthreads();
    for (int o = 128; o > 0; o >>= 1) {
        if (tid < o) red[tid] += red[tid + o];
        __syncthreads();
    }
    if (tid == 0) g_v[d] = red[0];
}

// ---------------- K2: energies via Gram quadratic form (packed f32x2) ----------------
// E(t,s) = x^T C[q:q+80, q:q+80] x + 2 v[q:q+80].x  (const dropped: argmax-safe)
// launch #4 -> profiled. launch_bounds(128,3): cap ~170 regs, guarantee 3 warps/SMSP.
#define NS 8
#define CROWS 87
#define CPITCH 96
__global__ __launch_bounds__(128, 3) void energy_kernel(const float* __restrict__ x) {
    __shared__ __align__(16) float Cs[CROWS * CPITCH];
    __shared__ float xs[32 * 81];
    __shared__ float vs[WIN];

    int tid = threadIdx.x;
    int lane = tid & 31;
    int w = tid >> 5;
    int tb = blockIdx.x * 32;
    int s0 = blockIdx.y * NS;
    int qlo = 73 - s0; if (qlo < 0) qlo = 0;

    for (int i = tid; i < CROWS * CPITCH; i += 128) Cs[i] = 0.f;
    __syncthreads();
    for (int i = tid; i < CROWS * CROWS; i += 128) {
        int r = i / CROWS, c = i - r * CROWS;
        Cs[r * CPITCH + 4 + c] = g_C[(qlo + r) * WIN + qlo + c];
    }
    for (int i = tid; i < 32 * IDIM; i += 128) {
        int tok = i / IDIM, ii = i - tok * IDIM;
        xs[tok * 81 + ii] = x[(tb + tok) * IDIM + ii];
    }
    for (int i = tid; i < WIN; i += 128) vs[i] = g_v[i];
    __syncthreads();

    const float* myx = &xs[lane * 81];
    unsigned long long best = 0ull;

#pragma unroll 1
    for (int si = 0; si < 2; si++) {
        int s = s0 + w + si * 4;
        if (s > 80) continue;
        int q = 80 - s;
        int coff = q - qlo;           // 0..7
        int p = coff & 3;
        int cbase = 4 + coff - p;     // multiple of 4 -> 16B-aligned loads

        // packed x pairs, pre-shifted by p
        unsigned long long xp[42];
#pragma unroll
        for (int j = 0; j < 42; j++) {
            int k0 = 2 * j - p, k1 = 2 * j + 1 - p;
            float lo = (k0 >= 0 && k0 < IDIM) ? myx[k0] : 0.f;
            float hi = (k1 >= 0 && k1 < IDIM) ? myx[k1] : 0.f;
            PACK2(xp[j], lo, hi);
        }

        float acc = 0.f;
        for (int i = 0; i < IDIM; i++) {
            const ulonglong2* cr =
                reinterpret_cast<const ulonglong2*>(&Cs[(coff + i) * CPITCH + cbase]);
            unsigned long long pc0 = 0ull, pc1 = 0ull, pc2 = 0ull, pc3 = 0ull;
#pragma unroll
            for (int j4 = 0; j4 < 21; j4++) {
                ulonglong2 cv = cr[j4];
                if (j4 & 1) {
                    FFMA2_ACC(pc2, cv.x, xp[2 * j4]);
                    FFMA2_ACC(pc3, cv.y, xp[2 * j4 + 1]);
                } else {
                    FFMA2_ACC(pc0, cv.x, xp[2 * j4]);
                    FFMA2_ACC(pc1, cv.y, xp[2 * j4 + 1]);
                }
            }
            unsigned long long s01, s23, st;
            ADD2(s01, pc0, pc1);
            ADD2(s23, pc2, pc3);
            ADD2(st, s01, s23);
            float rl, rh;
            UNPACK2(rl, rh, st);
            acc += myx[i] * (rl + rh);
        }

        float cross = 0.f;
        for (int i = 0; i < IDIM; i++) cross += myx[i] * vs[q + i];
        float E = acc + 2.f * cross;

        unsigned eb = __float_as_uint(E);
        unsigned key = eb ^ (unsigned)(((int)eb >> 31) | 0x80000000);
        unsigned long long pk = ((unsigned long long)key << 32) | (unsigned)q;
        if (pk > best) best = pk;
    }
    if (best) atomicMax(&g_packed[tb + lane], best);
}

// ---------------- K3: h for winning shift, 8 tokens/block, coalesced WeT ----------------
__global__ __launch_bounds__(256) void hcompute_kernel(
    const float* __restrict__ x, const float* __restrict__ b_enc,
    const int* __restrict__ mask_prev)
{
    __shared__ float xsp[TPB][WIN];
    __shared__ int qs[TPB];
    int tid = threadIdx.x;
    int tb = blockIdx.x * TPB;

    if (tid < TPB) qs[tid] = (int)(g_packed[tb + tid] & 0xFFFFFFFFull);
    for (int i = tid; i < TPB * WIN; i += 256) ((float*)xsp)[i] = 0.f;
    __syncthreads();
    for (int idx = tid; idx < TPB * IDIM; idx += 256) {
        int t = idx / IDIM, a = idx - t * IDIM;
        xsp[t][qs[t] + a] = x[(tb + t) * IDIM + a];
    }
    __syncthreads();

    int j0 = 2 * tid;
    float a0[TPB], a1[TPB];
#pragma unroll
    for (int t = 0; t < TPB; t++) { a0[t] = 0.f; a1[t] = 0.f; }

    for (int i = 0; i < WIN; i++) {
        float2 c = *reinterpret_cast<const float2*>(&g_WeT[i * HDIM + j0]);
#pragma unroll
        for (int t = 0; t < TPB; t++) {
            float xv = xsp[t][i];
            a0[t] += xv * c.x;
            a1[t] += xv * c.y;
        }
    }

    float bb0 = b_enc[j0], bb1 = b_enc[j0 + 1];
#pragma unroll
    for (int t = 0; t < TPB; t++) {
        int tg = tb + t;
        int2 m = *reinterpret_cast<const int2*>(&mask_prev[tg * HDIM + j0]);
        float h0 = a0[t] + bb0; if (m.x != 0) h0 = 0.f;
        float h1 = a1[t] + bb1; if (m.y != 0) h1 = 0.f;
        *reinterpret_cast<float2*>(&g_h[tg * HDIM + j0]) = make_float2(h0, h1);
    }
}

// ---------------- K4: exact top-128 via MSD radix select + sparse decoder ----------------
__global__ __launch_bounds__(256) void sortdecode_kernel(
    const float* __restrict__ b_dec, float* __restrict__ out)
{
    __shared__ float hs[HDIM];
    __shared__ int hist[256];
    __shared__ unsigned selbits[16];
    __shared__ unsigned eqbits[16];
    __shared__ int sPrefix, sR, sGt;
    __shared__ float selv[KSEL];
    __shared__ int   selj[KSEL];
    __shared__ float psum[240];

    int t = blockIdx.x;
    int tid = threadIdx.x;
    int q = (int)(g_packed[t] & 0xFFFFFFFFull);

    float h0 = g_h[t * HDIM + tid];
    float h1 = g_h[t * HDIM + tid + 256];
    hs[tid] = h0;
    hs[tid + 256] = h1;
    unsigned v0 = __float_as_uint(h0 * h0);   // >=0 -> bit-monotonic
    unsigned v1 = __float_as_uint(h1 * h1);
    if (tid == 0) { sPrefix = 0; sR = KSEL; sGt = 0; }
    if (tid < 16) { selbits[tid] = 0u; eqbits[tid] = 0u; }
    __syncthreads();

#pragma unroll
    for (int pass = 0; pass < 4; pass++) {
        int shift = 24 - 8 * pass;
        if (tid < 256) hist[tid] = 0;
        __syncthreads();
        int prefix = sPrefix;
        bool act0 = (pass == 0) || ((v0 >> (shift + 8)) == (unsigned)(prefix >> (shift + 8)));
        bool act1 = (pass == 0) || ((v1 >> (shift + 8)) == (unsigned)(prefix >> (shift + 8)));
        if (act0) atomicAdd(&hist[(v0 >> shift) & 255], 1);
        if (act1) atomicAdd(&hist[(v1 >> shift) & 255], 1);
        __syncthreads();
        if (tid < 32) {
            int lane = tid;
            int base = 255 - lane * 8;
            int c[8], lsum = 0;
#pragma unroll
            for (int i = 0; i < 8; i++) { c[i] = hist[base - i]; lsum += c[i]; }
            int xsc = lsum;
#pragma unroll
            for (int o = 1; o < 32; o <<= 1) {
                int y = __shfl_up_sync(0xffffffffu, xsc, o);
                if (lane >= o) xsc += y;
            }
            int pref = xsc - lsum;
            int r = sR;
            if (pref < r && r <= pref + lsum) {
                int run = pref, d = -1, gt_add = 0;
#pragma unroll
                for (int i = 0; i < 8; i++) {
                    if (d < 0 && run + c[i] >= r) { d = base - i; gt_add = run; }
                    run += c[i];
                }
                sPrefix = prefix | (d << shift);
                sR = r - gt_add;
                sGt = sGt + gt_add;
            }
        }
        __syncthreads();
    }

    unsigned Tv = (unsigned)sPrefix;
    int need_eq = KSEL - sGt;

    if (v0 > Tv) atomicOr(&selbits[tid >> 5], 1u << (tid & 31));
    else if (v0 == Tv) atomicOr(&eqbits[tid >> 5], 1u << (tid & 31));
    {
        int j = tid + 256;
        if (v1 > Tv) atomicOr(&selbits[j >> 5], 1u << (j & 31));
        else if (v1 == Tv) atomicOr(&eqbits[j >> 5], 1u << (j & 31));
    }
    __syncthreads();

#pragma unroll
    for (int e = 0; e < 2; e++) {
        int j = tid + 256 * e;
        unsigned vv = (e == 0) ? v0 : v1;
        if (vv == Tv) {
            int w = j >> 5;
            int rk = __popc(eqbits[w] & ((1u << (j & 31)) - 1u));
            for (int u = 0; u < w; u++) rk += __popc(eqbits[u]);
            if (rk < need_eq) atomicOr(&selbits[w], 1u << (j & 31));
        }
    }
    __syncthreads();

#pragma unroll
    for (int e = 0; e < 2; e++) {
        int j = tid + 256 * e;
        int w = j >> 5;
        if (selbits[w] & (1u << (j & 31))) {
            int slot = __popc(selbits[w] & ((1u << (j & 31)) - 1u));
            for (int u = 0; u < w; u++) slot += __popc(selbits[u]);
            selj[slot] = j;
            selv[slot] = hs[j];
        }
    }
    __syncthreads();

    if (tid < 240) {
        int g = tid / IDIM;
        int i = tid - g * IDIM;
        int k0 = (g == 0) ? 0 : (g == 1 ? 43 : 86);
        int k1 = (g == 0) ? 43 : (g == 1 ? 86 : KSEL);
        float a = 0.f;
        for (int k = k0; k < k1; k++)
            a += selv[k] * g_WdT[selj[k] * WIN + q + i];
        psum[tid] = a;
    }
    __syncthreads();
    if (tid < IDIM)
        out[t * IDIM + tid] = psum[tid] + psum[IDIM + tid] + psum[2 * IDIM + tid]
                            + b_dec[q + tid];
}

// ---------------- launch ----------------
extern "C" void kernel_launch(void* const* d_in, const int* in_sizes, int n_in,
                              void* d_out, int out_size) {
    const float* x        = (const float*)d_in[0];
    const float* W_enc    = (const float*)d_in[1];
    const float* b_enc    = (const float*)d_in[2];
    const float* W_dec    = (const float*)d_in[3];
    const float* b_dec    = (const float*)d_in[4];
    const int*   mask_prev= (const int*)d_in[5];
    float* out = (float*)d_out;

    prep1_kernel<<<26, 256>>>(W_enc);                 // gram + zero
    prep2_kernel<<<160, 256>>>(W_enc, W_dec);         // transposes
    prep3_kernel<<<WIN, 256>>>(W_enc, b_enc);         // vb
    energy_kernel<<<dim3(64, 11), 128>>>(x);          // launch #4 -> profiled
    hcompute_kernel<<<NTOK / TPB, 256>>>(x, b_enc, mask_prev);
    sortdecode_kernel<<<NTOK, 256>>>(b_dec, out);
}

// round 10
// speedup vs baseline: 2.3133x; 1.1111x over previous
#include <cuda_runtime.h>
#include <cuda_bf16.h>
#include <cstdint>

// Problem constants
#define IDIM   80
#define HDIM   512
#define WIN    160      // IN_EXTRA + IDIM
#define NSHIFT 81       // IN_EXTRA + 1
#define NTOK   2048     // B*T
#define KSEL   128      // 2*CDIM
#define TPB    8        // tokens per hcompute block

// packed f32x2 helpers (Blackwell sm_100a+)
#define FFMA2_ACC(acc, a, b) \
    asm("fma.rn.f32x2 %0, %1, %2, %0;" : "+l"(acc) : "l"(a), "l"(b))
#define ADD2(d, a, b) \
    asm("add.rn.f32x2 %0, %1, %2;" : "=l"(d) : "l"(a), "l"(b))
#define PACK2(d, lo, hi) \
    asm("mov.b64 %0, {%1, %2};" : "=l"(d) : "f"(lo), "f"(hi))
#define UNPACK2(lo, hi, v) \
    asm("mov.b64 {%0, %1}, %2;" : "=f"(lo), "=f"(hi) : "l"(v))

// ---------------- scratch (__device__ globals; no allocation) ----------------
__device__ float g_C[WIN * WIN];            // Gram matrix W_enc^T W_enc (160x160)
__device__ float g_v[WIN];                  // W_enc^T b_enc
__device__ unsigned long long g_packed[NTOK]; // (ordered(E)<<32)|q  via atomicMax
__device__ float g_WeT[WIN * HDIM];         // W_enc transposed
__device__ float g_WdT[HDIM * WIN];         // W_dec transposed
__device__ float g_h[NTOK * HDIM];          // masked h per token

// ---------------- K1a: gram + zero ----------------
__global__ __launch_bounds__(256) void prep1_kernel(const float* __restrict__ W_enc) {
    int blk = blockIdx.x;
    int tid = threadIdx.x;
    if (blk < 25) {
        __shared__ float SA[8][32];
        __shared__ float SB[8][32];
        int d0 = (blk % 5) * 32, e0 = (blk / 5) * 32;
        int dd = tid >> 5, ee = tid & 31;
        float a0 = 0.f, a1 = 0.f, a2 = 0.f, a3 = 0.f;
        for (int j0 = 0; j0 < HDIM; j0 += 8) {
            SA[dd][ee] = W_enc[(j0 + dd) * WIN + d0 + ee];
            SB[dd][ee] = W_enc[(j0 + dd) * WIN + e0 + ee];
            __syncthreads();
#pragma unroll
            for (int jj = 0; jj < 8; jj++) {
                float b = SB[jj][ee];
                a0 += SA[jj][dd] * b;
                a1 += SA[jj][dd + 8] * b;
                a2 += SA[jj][dd + 16] * b;
                a3 += SA[jj][dd + 24] * b;
            }
            __syncthreads();
        }
        g_C[(d0 + dd) * WIN + e0 + ee]      = a0;
        g_C[(d0 + dd + 8) * WIN + e0 + ee]  = a1;
        g_C[(d0 + dd + 16) * WIN + e0 + ee] = a2;
        g_C[(d0 + dd + 24) * WIN + e0 + ee] = a3;
    } else {
        for (int i = tid; i < NTOK; i += 256) g_packed[i] = 0ull;
    }
}

// ---------------- K1b: transposes ----------------
__global__ __launch_bounds__(256) void prep2_kernel(
    const float* __restrict__ W_enc, const float* __restrict__ W_dec)
{
    __shared__ float tile[32][33];
    int blk = blockIdx.x;
    int tid = threadIdx.x;
    int tx = tid & 31, ty = tid >> 5;
    if (blk < 80) {
        int bx = (blk % 5) * 32;
        int by = (blk / 5) * 32;
#pragma unroll
        for (int r = 0; r < 4; r++)
            tile[ty + 8 * r][tx] = W_enc[(by + ty + 8 * r) * WIN + bx + tx];
        __syncthreads();
#pragma unroll
        for (int r = 0; r < 4; r++)
            g_WeT[(bx + ty + 8 * r) * HDIM + by + tx] = tile[tx][ty + 8 * r];
    } else {
        int bi = blk - 80;
        int bx = (bi / 5) * 32;
        int by = (bi % 5) * 32;
#pragma unroll
        for (int r = 0; r < 4; r++)
            tile[ty + 8 * r][tx] = W_dec[(by + ty + 8 * r) * HDIM + bx + tx];
        __syncthreads();
#pragma unroll
        for (int r = 0; r < 4; r++)
            g_WdT[(bx + ty + 8 * r) * WIN + by + tx] = tile[tx][ty + 8 * r];
    }
}

// ---------------- K1c: v = W^T b ----------------
__global__ __launch_bounds__(256) void prep3_kernel(
    const float* __restrict__ W_enc, const float* __restrict__ b_enc)
{
    __shared__ float red[256];
    int d = blockIdx.x;
    int tid = threadIdx.x;
    float a = b_enc[tid] * W_enc[tid * WIN + d]
            + b_enc[tid + 256] * W_enc[(tid + 256) * WIN + d];
    red[tid] = a;
    __syncthreads();
    for (int o = 128; o > 0; o >>= 1) {
        if (tid < o) red[tid] += red[tid + o];
        __syncthreads();
    }
    if (tid == 0) g_v[d] = red[0];
}

// ---------------- K2: energies, dual-shift fused rows (packed f32x2) ----------------
// Warp w handles sA = s0+w and sB = sA+4. Both have alignment p = 3-w, so one
// padded-x array xp[] and ONE 22-float4 C-row load serve both shifts:
//   padded col n -> C[qlo + row][qlo + n - 4]; multiplies x[n-8-p] (A) / x[n-4-p] (B).
#define NS 8
#define CROWS 87
#define CPITCH 96
__global__ __launch_bounds__(128, 3) void energy_kernel(const float* __restrict__ x) {
    __shared__ __align__(16) float Cs[CROWS * CPITCH];
    __shared__ float xs[32 * 81];
    __shared__ float vs[WIN];

    int tid = threadIdx.x;
    int lane = tid & 31;
    int w = tid >> 5;
    int tb = blockIdx.x * 32;
    int s0 = blockIdx.y * NS;
    int qlo = 73 - s0; if (qlo < 0) qlo = 0;

    for (int i = tid; i < CROWS * CPITCH; i += 128) Cs[i] = 0.f;
    __syncthreads();
    for (int i = tid; i < CROWS * CROWS; i += 128) {
        int r = i / CROWS, c = i - r * CROWS;
        Cs[r * CPITCH + 4 + c] = g_C[(qlo + r) * WIN + qlo + c];
    }
    for (int i = tid; i < 32 * IDIM; i += 128) {
        int tok = i / IDIM, ii = i - tok * IDIM;
        xs[tok * 81 + ii] = x[(tb + tok) * IDIM + ii];
    }
    for (int i = tid; i < WIN; i += 128) vs[i] = g_v[i];
    __syncthreads();

    const float* myx = &xs[lane * 81];
    unsigned long long best = 0ull;

    if (s0 < 80) {
        // ---- fused dual-shift path (both sA and sB valid) ----
        int sA = s0 + w;
        int qA = 80 - sA, qB = qA - 4;
        int p = 3 - w;            // = coffA&3 = coffB&3
        int coffB = 3 - w;        // qB - qlo

        unsigned long long xp[44];   // xp[j] = (x[2j-p], x[2j+1-p])
#pragma unroll
        for (int j = 0; j < 44; j++) {
            int k0 = 2 * j - p, k1 = 2 * j + 1 - p;
            float lo = (k0 >= 0 && k0 < IDIM) ? myx[k0] : 0.f;
            float hi = (k1 >= 0 && k1 < IDIM) ? myx[k1] : 0.f;
            PACK2(xp[j], lo, hi);
        }

        unsigned long long accA = 0ull, accB = 0ull;
        const float* base = &Cs[coffB * CPITCH + 4];

#pragma unroll 2
        for (int r = 0; r < 84; r++) {
            const ulonglong2* cr = reinterpret_cast<const ulonglong2*>(base + r * CPITCH);
            unsigned long long pA0 = 0ull, pA1 = 0ull, pB0 = 0ull, pB1 = 0ull;
#pragma unroll
            for (int k = 0; k < 22; k++) {
                ulonglong2 cv = cr[k];
                if (k <= 20) {
                    FFMA2_ACC(pB0, cv.x, xp[2 * k]);
                    FFMA2_ACC(pB1, cv.y, xp[2 * k + 1]);
                }
                if (k >= 1) {
                    FFMA2_ACC(pA0, cv.x, xp[2 * k - 2]);
                    FFMA2_ACC(pA1, cv.y, xp[2 * k - 1]);
                }
            }
            if (r < 80) {            // shift B row r
                unsigned long long sB2, mp;
                ADD2(sB2, pB0, pB1);
                float mv = myx[r];
                PACK2(mp, mv, mv);
                FFMA2_ACC(accB, mp, sB2);
            }
            if (r >= 4) {            // shift A row r-4
                unsigned long long sA2, mp;
                ADD2(sA2, pA0, pA1);
                float mv = myx[r - 4];
                PACK2(mp, mv, mv);
                FFMA2_ACC(accA, mp, sA2);
            }
        }

        float crossA = 0.f, crossB = 0.f;
#pragma unroll 4
        for (int i = 0; i < IDIM; i++) {
            float xv = myx[i];
            crossA += xv * vs[qA + i];
            crossB += xv * vs[qB + i];
        }

        float alo, ahi, blo, bhi;
        UNPACK2(alo, ahi, accA);
        UNPACK2(blo, bhi, accB);
        float EA = (alo + ahi) + 2.f * crossA;
        float EB = (blo + bhi) + 2.f * crossB;

        unsigned ea = __float_as_uint(EA);
        unsigned keyA = ea ^ (unsigned)(((int)ea >> 31) | 0x80000000);
        unsigned eb = __float_as_uint(EB);
        unsigned keyB = eb ^ (unsigned)(((int)eb >> 31) | 0x80000000);
        unsigned long long pkA = ((unsigned long long)keyA << 32) | (unsigned)qA;
        unsigned long long pkB = ((unsigned long long)keyB << 32) | (unsigned)qB;
        best = pkA > pkB ? pkA : pkB;
    } else if (w == 0) {
        // ---- single-shift tail: s = 80, q = 0, qlo = 0, coff = 0, p = 0 ----
        unsigned long long xp[42];   // xp[j] = (x[2j], x[2j+1])
#pragma unroll
        for (int j = 0; j < 42; j++) {
            int k0 = 2 * j, k1 = 2 * j + 1;
            float lo = (k0 < IDIM) ? myx[k0] : 0.f;
            float hi = (k1 < IDIM) ? myx[k1] : 0.f;
            PACK2(xp[j], lo, hi);
        }
        unsigned long long acc = 0ull;
#pragma unroll 2
        for (int r = 0; r < IDIM; r++) {
            const ulonglong2* cr = reinterpret_cast<const ulonglong2*>(&Cs[r * CPITCH + 4]);
            unsigned long long p0 = 0ull, p1 = 0ull;
#pragma unroll
            for (int k = 0; k < 21; k++) {
                ulonglong2 cv = cr[k];
                FFMA2_ACC(p0, cv.x, xp[2 * k]);
                FFMA2_ACC(p1, cv.y, xp[2 * k + 1]);
            }
            unsigned long long sm, mp;
            ADD2(sm, p0, p1);
            float mv = myx[r];
            PACK2(mp, mv, mv);
            FFMA2_ACC(acc, mp, sm);
        }
        float cross = 0.f;
#pragma unroll 4
        for (int i = 0; i < IDIM; i++) cross += myx[i] * vs[i];
        float lo2, hi2;
        UNPACK2(lo2, hi2, acc);
        float E = (lo2 + hi2) + 2.f * cross;
        unsigned eb = __float_as_uint(E);
        unsigned key = eb ^ (unsigned)(((int)eb >> 31) | 0x80000000);
        best = ((unsigned long long)key << 32);   // q = 0
    }

    if (best) atomicMax(&g_packed[tb + lane], best);
}

// ---------------- K3: h for winning shift, 8 tokens/block, coalesced WeT ----------------
__global__ __launch_bounds__(256) void hcompute_kernel(
    const float* __restrict__ x, const float* __restrict__ b_enc,
    const int* __restrict__ mask_prev)
{
    __shared__ float xsp[TPB][WIN];
    __shared__ int qs[TPB];
    int tid = threadIdx.x;
    int tb = blockIdx.x * TPB;

    if (tid < TPB) qs[tid] = (int)(g_packed[tb + tid] & 0xFFFFFFFFull);
    for (int i = tid; i < TPB * WIN; i += 256) ((float*)xsp)[i] = 0.f;
    __syncthreads();
    for (int idx = tid; idx < TPB * IDIM; idx += 256) {
        int t = idx / IDIM, a = idx - t * IDIM;
        xsp[t][qs[t] + a] = x[(tb + t) * IDIM + a];
    }
    __syncthreads();

    int j0 = 2 * tid;
    float a0[TPB], a1[TPB];
#pragma unroll
    for (int t = 0; t < TPB; t++) { a0[t] = 0.f; a1[t] = 0.f; }

    for (int i = 0; i < WIN; i++) {
        float2 c = *reinterpret_cast<const float2*>(&g_WeT[i * HDIM + j0]);
#pragma unroll
        for (int t = 0; t < TPB; t++) {
            float xv = xsp[t][i];
            a0[t] += xv * c.x;
            a1[t] += xv * c.y;
        }
    }

    float bb0 = b_enc[j0], bb1 = b_enc[j0 + 1];
#pragma unroll
    for (int t = 0; t < TPB; t++) {
        int tg = tb + t;
        int2 m = *reinterpret_cast<const int2*>(&mask_prev[tg * HDIM + j0]);
        float h0 = a0[t] + bb0; if (m.x != 0) h0 = 0.f;
        float h1 = a1[t] + bb1; if (m.y != 0) h1 = 0.f;
        *reinterpret_cast<float2*>(&g_h[tg * HDIM + j0]) = make_float2(h0, h1);
    }
}

// ---------------- K4: exact top-128 via MSD radix select + sparse decoder ----------------
__global__ __launch_bounds__(256) void sortdecode_kernel(
    const float* __restrict__ b_dec, float* __restrict__ out)
{
    __shared__ float hs[HDIM];
    __shared__ int hist[256];
    __shared__ unsigned selbits[16];
    __shared__ unsigned eqbits[16];
    __shared__ int sPrefix, sR, sGt;
    __shared__ float selv[KSEL];
    __shared__ int   selj[KSEL];
    __shared__ float psum[240];

    int t = blockIdx.x;
    int tid = threadIdx.x;
    int q = (int)(g_packed[t] & 0xFFFFFFFFull);

    float h0 = g_h[t * HDIM + tid];
    float h1 = g_h[t * HDIM + tid + 256];
    hs[tid] = h0;
    hs[tid + 256] = h1;
    unsigned v0 = __float_as_uint(h0 * h0);   // >=0 -> bit-monotonic
    unsigned v1 = __float_as_uint(h1 * h1);
    if (tid == 0) { sPrefix = 0; sR = KSEL; sGt = 0; }
    if (tid < 16) { selbits[tid] = 0u; eqbits[tid] = 0u; }
    __syncthreads();

#pragma unroll
    for (int pass = 0; pass < 4; pass++) {
        int shift = 24 - 8 * pass;
        if (tid < 256) hist[tid] = 0;
        __syncthreads();
        int prefix = sPrefix;
        bool act0 = (pass == 0) || ((v0 >> (shift + 8)) == (unsigned)(prefix >> (shift + 8)));
        bool act1 = (pass == 0) || ((v1 >> (shift + 8)) == (unsigned)(prefix >> (shift + 8)));
        if (act0) atomicAdd(&hist[(v0 >> shift) & 255], 1);
        if (act1) atomicAdd(&hist[(v1 >> shift) & 255], 1);
        __syncthreads();
        if (tid < 32) {
            int lane = tid;
            int base = 255 - lane * 8;
            int c[8], lsum = 0;
#pragma unroll
            for (int i = 0; i < 8; i++) { c[i] = hist[base - i]; lsum += c[i]; }
            int xsc = lsum;
#pragma unroll
            for (int o = 1; o < 32; o <<= 1) {
                int y = __shfl_up_sync(0xffffffffu, xsc, o);
                if (lane >= o) xsc += y;
            }
            int pref = xsc - lsum;
            int r = sR;
            if (pref < r && r <= pref + lsum) {
                int run = pref, d = -1, gt_add = 0;
#pragma unroll
                for (int i = 0; i < 8; i++) {
                    if (d < 0 && run + c[i] >= r) { d = base - i; gt_add = run; }
                    run += c[i];
                }
                sPrefix = prefix | (d << shift);
                sR = r - gt_add;
                sGt = sGt + gt_add;
            }
        }
        __syncthreads();
    }

    unsigned Tv = (unsigned)sPrefix;
    int need_eq = KSEL - sGt;

    if (v0 > Tv) atomicOr(&selbits[tid >> 5], 1u << (tid & 31));
    else if (v0 == Tv) atomicOr(&eqbits[tid >> 5], 1u << (tid & 31));
    {
        int j = tid + 256;
        if (v1 > Tv) atomicOr(&selbits[j >> 5], 1u << (j & 31));
        else if (v1 == Tv) atomicOr(&eqbits[j >> 5], 1u << (j & 31));
    }
    __syncthreads();

#pragma unroll
    for (int e = 0; e < 2; e++) {
        int j = tid + 256 * e;
        unsigned vv = (e == 0) ? v0 : v1;
        if (vv == Tv) {
            int w = j >> 5;
            int rk = __popc(eqbits[w] & ((1u << (j & 31)) - 1u));
            for (int u = 0; u < w; u++) rk += __popc(eqbits[u]);
            if (rk < need_eq) atomicOr(&selbits[w], 1u << (j & 31));
        }
    }
    __syncthreads();

#pragma unroll
    for (int e = 0; e < 2; e++) {
        int j = tid + 256 * e;
        int w = j >> 5;
        if (selbits[w] & (1u << (j & 31))) {
            int slot = __popc(selbits[w] & ((1u << (j & 31)) - 1u));
            for (int u = 0; u < w; u++) slot += __popc(selbits[u]);
            selj[slot] = j;
            selv[slot] = hs[j];
        }
    }
    __syncthreads();

    if (tid < 240) {
        int g = tid / IDIM;
        int i = tid - g * IDIM;
        int k0 = (g == 0) ? 0 : (g == 1 ? 43 : 86);
        int k1 = (g == 0) ? 43 : (g == 1 ? 86 : KSEL);
        float a = 0.f;
        for (int k = k0; k < k1; k++)
            a += selv[k] * g_WdT[selj[k] * WIN + q + i];
        psum[tid] = a;
    }
    __syncthreads();
    if (tid < IDIM)
        out[t * IDIM + tid] = psum[tid] + psum[IDIM + tid] + psum[2 * IDIM + tid]
                            + b_dec[q + tid];
}

// ---------------- launch ----------------
extern "C" void kernel_launch(void* const* d_in, const int* in_sizes, int n_in,
                              void* d_out, int out_size) {
    const float* x        = (const float*)d_in[0];
    const float* W_enc    = (const float*)d_in[1];
    const float* b_enc    = (const float*)d_in[2];
    const float* W_dec    = (const float*)d_in[3];
    const float* b_dec    = (const float*)d_in[4];
    const int*   mask_prev= (const int*)d_in[5];
    float* out = (float*)d_out;

    prep1_kernel<<<26, 256>>>(W_enc);                 // gram + zero
    prep2_kernel<<<160, 256>>>(W_enc, W_dec);         // transposes
    prep3_kernel<<<WIN, 256>>>(W_enc, b_enc);         // vb
    energy_kernel<<<dim3(64, 11), 128>>>(x);          // launch #4 -> profiled
    hcompute_kernel<<<NTOK / TPB, 256>>>(x, b_enc, mask_prev);
    sortdecode_kernel<<<NTOK, 256>>>(b_dec, out);
}

// round 12
// speedup vs baseline: 2.4370x; 1.0535x over previous
#include <cuda_runtime.h>
#include <cuda_bf16.h>
#include <cstdint>

// Problem constants
#define IDIM   80
#define HDIM   512
#define WIN    160      // IN_EXTRA + IDIM
#define NSHIFT 81       // IN_EXTRA + 1
#define NTOK   2048     // B*T
#define KSEL   128      // 2*CDIM
#define TPB    8        // tokens per hcompute block

// packed f32x2 helpers (Blackwell sm_100a+)
#define FFMA2_ACC(acc, a, b) \
    asm("fma.rn.f32x2 %0, %1, %2, %0;" : "+l"(acc) : "l"(a), "l"(b))
#define ADD2(d, a, b) \
    asm("add.rn.f32x2 %0, %1, %2;" : "=l"(d) : "l"(a), "l"(b))
#define PACK2(d, lo, hi) \
    asm("mov.b64 %0, {%1, %2};" : "=l"(d) : "f"(lo), "f"(hi))
#define UNPACK2(lo, hi, v) \
    asm("mov.b64 {%0, %1}, %2;" : "=f"(lo), "=f"(hi) : "l"(v))

// ---------------- scratch (__device__ globals; no allocation) ----------------
__device__ float g_C[WIN * WIN];            // Gram matrix W_enc^T W_enc (160x160)
__device__ float g_v[WIN];                  // W_enc^T b_enc
__device__ unsigned long long g_packed[NTOK]; // (ordered(E)<<32)|q  via atomicMax
__device__ float g_WeT[WIN * HDIM];         // W_enc transposed
__device__ float g_WdT[HDIM * WIN];         // W_dec transposed
__device__ float g_h[NTOK * HDIM];          // masked h per token

// ---------------- K1: fused prep (gram + transposes + vb + zero) ----------------
// blocks 0..24: gram tile; 25..104: WeT; 105..184: WdT; 185..344: vb; 345: zero
__global__ __launch_bounds__(256) void prep_kernel(
    const float* __restrict__ W_enc, const float* __restrict__ b_enc,
    const float* __restrict__ W_dec)
{
    int blk = blockIdx.x;
    int tid = threadIdx.x;

    if (blk < 25) {
        __shared__ float SA[8][32];
        __shared__ float SB[8][32];
        int d0 = (blk % 5) * 32, e0 = (blk / 5) * 32;
        int dd = tid >> 5, ee = tid & 31;
        float a0 = 0.f, a1 = 0.f, a2 = 0.f, a3 = 0.f;
        for (int j0 = 0; j0 < HDIM; j0 += 8) {
            SA[dd][ee] = W_enc[(j0 + dd) * WIN + d0 + ee];
            SB[dd][ee] = W_enc[(j0 + dd) * WIN + e0 + ee];
            __syncthreads();
#pragma unroll
            for (int jj = 0; jj < 8; jj++) {
                float b = SB[jj][ee];
                a0 += SA[jj][dd] * b;
                a1 += SA[jj][dd + 8] * b;
                a2 += SA[jj][dd + 16] * b;
                a3 += SA[jj][dd + 24] * b;
            }
            __syncthreads();
        }
        g_C[(d0 + dd) * WIN + e0 + ee]      = a0;
        g_C[(d0 + dd + 8) * WIN + e0 + ee]  = a1;
        g_C[(d0 + dd + 16) * WIN + e0 + ee] = a2;
        g_C[(d0 + dd + 24) * WIN + e0 + ee] = a3;
    } else if (blk < 105) {
        __shared__ float tile[32][33];
        int bi = blk - 25;
        int bx = (bi % 5) * 32;
        int by = (bi / 5) * 32;
        int tx = tid & 31, ty = tid >> 5;
#pragma unroll
        for (int r = 0; r < 4; r++)
            tile[ty + 8 * r][tx] = W_enc[(by + ty + 8 * r) * WIN + bx + tx];
        __syncthreads();
#pragma unroll
        for (int r = 0; r < 4; r++)
            g_WeT[(bx + ty + 8 * r) * HDIM + by + tx] = tile[tx][ty + 8 * r];
    } else if (blk < 185) {
        __shared__ float tile[32][33];
        int bi = blk - 105;
        int bx = (bi / 5) * 32;
        int by = (bi % 5) * 32;
        int tx = tid & 31, ty = tid >> 5;
#pragma unroll
        for (int r = 0; r < 4; r++)
            tile[ty + 8 * r][tx] = W_dec[(by + ty + 8 * r) * HDIM + bx + tx];
        __syncthreads();
#pragma unroll
        for (int r = 0; r < 4; r++)
            g_WdT[(bx + ty + 8 * r) * WIN + by + tx] = tile[tx][ty + 8 * r];
    } else if (blk < 345) {
        __shared__ float red[256];
        int d = blk - 185;
        float a = b_enc[tid] * W_enc[tid * WIN + d]
                + b_enc[tid + 256] * W_enc[(tid + 256) * WIN + d];
        red[tid] = a;
        __syncthreads();
        for (int o = 128; o > 0; o >>= 1) {
            if (tid < o) red[tid] += red[tid + o];
            __syncthreads();
        }
        if (tid == 0) g_v[d] = red[0];
    } else {
        for (int i = tid; i < NTOK; i += 256) g_packed[i] = 0ull;
    }
}

// ---------------- K2: energies, dual-shift fused rows (packed f32x2) ----------------
// Warp w handles sA = s0+w and sB = sA+4; both share alignment p = 3-w, so one
// xp[] array and one 22-float4 C-row sweep serve both shifts.
// launch_bounds(128,4): cap 128 regs -> 16 warps/SM (occupancy play; xp stays live).
#define NS 8
#define CROWS 87
#define CPITCH 96
__global__ __launch_bounds__(128, 4) void energy_kernel(const float* __restrict__ x) {
    __shared__ __align__(16) float Cs[CROWS * CPITCH];
    __shared__ float xs[32 * 81];
    __shared__ float vs[WIN];

    int tid = threadIdx.x;
    int lane = tid & 31;
    int w = tid >> 5;
    int tb = blockIdx.x * 32;
    int s0 = blockIdx.y * NS;
    int qlo = 73 - s0; if (qlo < 0) qlo = 0;

    for (int i = tid; i < CROWS * CPITCH; i += 128) Cs[i] = 0.f;
    __syncthreads();
    for (int i = tid; i < CROWS * CROWS; i += 128) {
        int r = i / CROWS, c = i - r * CROWS;
        Cs[r * CPITCH + 4 + c] = g_C[(qlo + r) * WIN + qlo + c];
    }
    for (int i = tid; i < 32 * IDIM; i += 128) {
        int tok = i / IDIM, ii = i - tok * IDIM;
        xs[tok * 81 + ii] = x[(tb + tok) * IDIM + ii];
    }
    for (int i = tid; i < WIN; i += 128) vs[i] = g_v[i];
    __syncthreads();

    const float* myx = &xs[lane * 81];
    unsigned long long best = 0ull;

    if (s0 < 80) {
        int sA = s0 + w;
        int qA = 80 - sA, qB = qA - 4;
        int p = 3 - w;            // = coffA&3 = coffB&3
        int coffB = 3 - w;        // qB - qlo

        unsigned long long xp[42];   // xp[j] = (x[2j-p], x[2j+1-p])
#pragma unroll
        for (int j = 0; j < 42; j++) {
            int k0 = 2 * j - p, k1 = 2 * j + 1 - p;
            float lo = (k0 >= 0 && k0 < IDIM) ? myx[k0] : 0.f;
            float hi = (k1 >= 0 && k1 < IDIM) ? myx[k1] : 0.f;
            PACK2(xp[j], lo, hi);
        }

        unsigned long long accA = 0ull, accB = 0ull;
        const float* base = &Cs[coffB * CPITCH + 4];

#pragma unroll 1
        for (int r = 0; r < 84; r++) {
            const ulonglong2* cr = reinterpret_cast<const ulonglong2*>(base + r * CPITCH);
            unsigned long long pA0 = 0ull, pA1 = 0ull, pB0 = 0ull, pB1 = 0ull;
#pragma unroll
            for (int k = 0; k < 22; k++) {
                ulonglong2 cv = cr[k];
                if (k <= 20) {
                    FFMA2_ACC(pB0, cv.x, xp[2 * k]);
                    FFMA2_ACC(pB1, cv.y, xp[2 * k + 1]);
                }
                if (k >= 1) {
                    FFMA2_ACC(pA0, cv.x, xp[2 * k - 2]);
                    FFMA2_ACC(pA1, cv.y, xp[2 * k - 1]);
                }
            }
            if (r < 80) {            // shift B row r
                unsigned long long sB2, mp;
                ADD2(sB2, pB0, pB1);
                float mv = myx[r];
                PACK2(mp, mv, mv);
                FFMA2_ACC(accB, mp, sB2);
            }
            if (r >= 4) {            // shift A row r-4
                unsigned long long sA2, mp;
                ADD2(sA2, pA0, pA1);
                float mv = myx[r - 4];
                PACK2(mp, mv, mv);
                FFMA2_ACC(accA, mp, sA2);
            }
        }

        float crossA = 0.f, crossB = 0.f;
#pragma unroll 4
        for (int i = 0; i < IDIM; i++) {
            float xv = myx[i];
            crossA += xv * vs[qA + i];
            crossB += xv * vs[qB + i];
        }

        float alo, ahi, blo, bhi;
        UNPACK2(alo, ahi, accA);
        UNPACK2(blo, bhi, accB);
        float EA = (alo + ahi) + 2.f * crossA;
        float EB = (blo + bhi) + 2.f * crossB;

        unsigned ea = __float_as_uint(EA);
        unsigned keyA = ea ^ (unsigned)(((int)ea >> 31) | 0x80000000);
        unsigned eb = __float_as_uint(EB);
        unsigned keyB = eb ^ (unsigned)(((int)eb >> 31) | 0x80000000);
        unsigned long long pkA = ((unsigned long long)keyA << 32) | (unsigned)qA;
        unsigned long long pkB = ((unsigned long long)keyB << 32) | (unsigned)qB;
        best = pkA > pkB ? pkA : pkB;
    } else if (w == 0) {
        // single-shift tail: s = 80, q = 0, qlo = 0, coff = 0, p = 0
        unsigned long long xp[42];
#pragma unroll
        for (int j = 0; j < 42; j++) {
            int k0 = 2 * j, k1 = 2 * j + 1;
            float lo = (k0 < IDIM) ? myx[k0] : 0.f;
            float hi = (k1 < IDIM) ? myx[k1] : 0.f;
            PACK2(xp[j], lo, hi);
        }
        unsigned long long acc = 0ull;
#pragma unroll 1
        for (int r = 0; r < IDIM; r++) {
            const ulonglong2* cr = reinterpret_cast<const ulonglong2*>(&Cs[r * CPITCH + 4]);
            unsigned long long p0 = 0ull, p1 = 0ull;
#pragma unroll
            for (int k = 0; k < 21; k++) {
                ulonglong2 cv = cr[k];
                FFMA2_ACC(p0, cv.x, xp[2 * k]);
                FFMA2_ACC(p1, cv.y, xp[2 * k + 1]);
            }
            unsigned long long sm, mp;
            ADD2(sm, p0, p1);
            float mv = myx[r];
            PACK2(mp, mv, mv);
            FFMA2_ACC(acc, mp, sm);
        }
        float cross = 0.f;
#pragma unroll 4
        for (int i = 0; i < IDIM; i++) cross += myx[i] * vs[i];
        float lo2, hi2;
        UNPACK2(lo2, hi2, acc);
        float E = (lo2 + hi2) + 2.f * cross;
        unsigned eb = __float_as_uint(E);
        unsigned key = eb ^ (unsigned)(((int)eb >> 31) | 0x80000000);
        best = ((unsigned long long)key << 32);   // q = 0
    }

    if (best) atomicMax(&g_packed[tb + lane], best);
}

// ---------------- K3: h for winning shift, 8 tokens/block, coalesced WeT ----------------
__global__ __launch_bounds__(256) void hcompute_kernel(
    const float* __restrict__ x, const float* __restrict__ b_enc,
    const int* __restrict__ mask_prev)
{
    __shared__ float xsp[TPB][WIN];
    __shared__ int qs[TPB];
    int tid = threadIdx.x;
    int tb = blockIdx.x * TPB;

    if (tid < TPB) qs[tid] = (int)(g_packed[tb + tid] & 0xFFFFFFFFull);
    for (int i = tid; i < TPB * WIN; i += 256) ((float*)xsp)[i] = 0.f;
    __syncthreads();
    for (int idx = tid; idx < TPB * IDIM; idx += 256) {
        int t = idx / IDIM, a = idx - t * IDIM;
        xsp[t][qs[t] + a] = x[(tb + t) * IDIM + a];
    }
    __syncthreads();

    int j0 = 2 * tid;
    float a0[TPB], a1[TPB];
#pragma unroll
    for (int t = 0; t < TPB; t++) { a0[t] = 0.f; a1[t] = 0.f; }

    for (int i = 0; i < WIN; i++) {
        float2 c = *reinterpret_cast<const float2*>(&g_WeT[i * HDIM + j0]);
#pragma unroll
        for (int t = 0; t < TPB; t++) {
            float xv = xsp[t][i];
            a0[t] += xv * c.x;
            a1[t] += xv * c.y;
        }
    }

    float bb0 = b_enc[j0], bb1 = b_enc[j0 + 1];
#pragma unroll
    for (int t = 0; t < TPB; t++) {
        int tg = tb + t;
        int2 m = *reinterpret_cast<const int2*>(&mask_prev[tg * HDIM + j0]);
        float h0 = a0[t] + bb0; if (m.x != 0) h0 = 0.f;
        float h1 = a1[t] + bb1; if (m.y != 0) h1 = 0.f;
        *reinterpret_cast<float2*>(&g_h[tg * HDIM + j0]) = make_float2(h0, h1);
    }
}

// ---------------- K4: exact top-128 via MSD radix select + sparse decoder ----------------
__global__ __launch_bounds__(256) void sortdecode_kernel(
    const float* __restrict__ b_dec, float* __restrict__ out)
{
    __shared__ float hs[HDIM];
    __shared__ int hist[256];
    __shared__ unsigned selbits[16];
    __shared__ unsigned eqbits[16];
    __shared__ int sPrefix, sR, sGt;
    __shared__ float selv[KSEL];
    __shared__ int   selj[KSEL];
    __shared__ float psum[240];

    int t = blockIdx.x;
    int tid = threadIdx.x;
    int q = (int)(g_packed[t] & 0xFFFFFFFFull);

    float h0 = g_h[t * HDIM + tid];
    float h1 = g_h[t * HDIM + tid + 256];
    hs[tid] = h0;
    hs[tid + 256] = h1;
    unsigned v0 = __float_as_uint(h0 * h0);   // >=0 -> bit-monotonic
    unsigned v1 = __float_as_uint(h1 * h1);
    if (tid == 0) { sPrefix = 0; sR = KSEL; sGt = 0; }
    if (tid < 16) { selbits[tid] = 0u; eqbits[tid] = 0u; }
    __syncthreads();

#pragma unroll
    for (int pass = 0; pass < 4; pass++) {
        int shift = 24 - 8 * pass;
        if (tid < 256) hist[tid] = 0;
        __syncthreads();
        int prefix = sPrefix;
        bool act0 = (pass == 0) || ((v0 >> (shift + 8)) == (unsigned)(prefix >> (shift + 8)));
        bool act1 = (pass == 0) || ((v1 >> (shift + 8)) == (unsigned)(prefix >> (shift + 8)));
        if (act0) atomicAdd(&hist[(v0 >> shift) & 255], 1);
        if (act1) atomicAdd(&hist[(v1 >> shift) & 255], 1);
        __syncthreads();
        if (tid < 32) {
            int lane = tid;
            int base = 255 - lane * 8;
            int c[8], lsum = 0;
#pragma unroll
            for (int i = 0; i < 8; i++) { c[i] = hist[base - i]; lsum += c[i]; }
            int xsc = lsum;
#pragma unroll
            for (int o = 1; o < 32; o <<= 1) {
                int y = __shfl_up_sync(0xffffffffu, xsc, o);
                if (lane >= o) xsc += y;
            }
            int pref = xsc - lsum;
            int r = sR;
            if (pref < r && r <= pref + lsum) {
                int run = pref, d = -1, gt_add = 0;
#pragma unroll
                for (int i = 0; i < 8; i++) {
                    if (d < 0 && run + c[i] >= r) { d = base - i; gt_add = run; }
                    run += c[i];
                }
                sPrefix = prefix | (d << shift);
                sR = r - gt_add;
                sGt = sGt + gt_add;
            }
        }
        __syncthreads();
    }

    unsigned Tv = (unsigned)sPrefix;
    int need_eq = KSEL - sGt;

    if (v0 > Tv) atomicOr(&selbits[tid >> 5], 1u << (tid & 31));
    else if (v0 == Tv) atomicOr(&eqbits[tid >> 5], 1u << (tid & 31));
    {
        int j = tid + 256;
        if (v1 > Tv) atomicOr(&selbits[j >> 5], 1u << (j & 31));
        else if (v1 == Tv) atomicOr(&eqbits[j >> 5], 1u << (j & 31));
    }
    __syncthreads();

#pragma unroll
    for (int e = 0; e < 2; e++) {
        int j = tid + 256 * e;
        unsigned vv = (e == 0) ? v0 : v1;
        if (vv == Tv) {
            int w = j >> 5;
            int rk = __popc(eqbits[w] & ((1u << (j & 31)) - 1u));
            for (int u = 0; u < w; u++) rk += __popc(eqbits[u]);
            if (rk < need_eq) atomicOr(&selbits[w], 1u << (j & 31));
        }
    }
    __syncthreads();

#pragma unroll
    for (int e = 0; e < 2; e++) {
        int j = tid + 256 * e;
        int w = j >> 5;
        if (selbits[w] & (1u << (j & 31))) {
            int slot = __popc(selbits[w] & ((1u << (j & 31)) - 1u));
            for (int u = 0; u < w; u++) slot += __popc(selbits[u]);
            selj[slot] = j;
            selv[slot] = hs[j];
        }
    }
    __syncthreads();

    if (tid < 240) {
        int g = tid / IDIM;
        int i = tid - g * IDIM;
        int k0 = (g == 0) ? 0 : (g == 1 ? 43 : 86);
        int k1 = (g == 0) ? 43 : (g == 1 ? 86 : KSEL);
        float a = 0.f;
        for (int k = k0; k < k1; k++)
            a += selv[k] * g_WdT[selj[k] * WIN + q + i];
        psum[tid] = a;
    }
    __syncthreads();
    if (tid < IDIM)
        out[t * IDIM + tid] = psum[tid] + psum[IDIM + tid] + psum[2 * IDIM + tid]
                            + b_dec[q + tid];
}

// ---------------- launch ----------------
extern "C" void kernel_launch(void* const* d_in, const int* in_sizes, int n_in,
                              void* d_out, int out_size) {
    const float* x        = (const float*)d_in[0];
    const float* W_enc    = (const float*)d_in[1];
    const float* b_enc    = (const float*)d_in[2];
    const float* W_dec    = (const float*)d_in[3];
    const float* b_dec    = (const float*)d_in[4];
    const int*   mask_prev= (const int*)d_in[5];
    float* out = (float*)d_out;

    prep_kernel<<<346, 256>>>(W_enc, b_enc, W_dec);
    energy_kernel<<<dim3(64, 11), 128>>>(x);
    hcompute_kernel<<<NTOK / TPB, 256>>>(x, b_enc, mask_prev);
    sortdecode_kernel<<<NTOK, 256>>>(b_dec, out);
}